// round 16
// baseline (speedup 1.0000x reference)
#include <cuda_runtime.h>
#include <cuda_fp16.h>
#include <cstdint>

#define NDIM   8
#define NPAIR  28
#define NH     128
#define DIN    6
#define TILE_M 128
#define THREADS 256
#define CTAS_PER_PAIR 10
#define LDHW   68            // h row stride in 32-bit words, conflict-free

// ---- smem layout (32-bit word offsets) ----
#define OFF_BF0  0                       // 8192 words (128x128 fp16 fragments)
#define OFF_BF1  8192
#define OFF_H    16384                   // 128*68 = 8704 (words 0..7 double as xg)
#define OFF_X    25088                   // 128*8 fp32 = 1024
#define OFF_W1F  26112                   // 1024 words: W1 one-K-step fragments (K=16 padded)
#define OFF_B1   27136
#define OFF_BH0  27264
#define OFF_BH1  27392
#define OFF_WO   27520
#define OFF_PR   27648
#define SMEM_WORDS 27776
#define SMEM_BYTES (SMEM_WORDS * 4)      // 111104 -> 2 CTAs/SM

// pair-group barrier: 64 threads (warps 2*mt, 2*mt+1), ids 1..4
#define PBAR(id) asm volatile("bar.sync %0, 64;" :: "r"((id) + 1) : "memory")

// softplus = max(v,0) + ln2*lg2(1 + 2^(-|v|*log2e)) : 6 instrs, 2 MUFU
__device__ __forceinline__ float softplus_f(float v) {
    float m = fmaxf(v, 0.0f);
    float y = -fabsf(v) * 1.4426950408889634f;     // folds into one FMUL
    float e;
    asm("ex2.approx.ftz.f32 %0, %1;" : "=f"(e) : "f"(y));
    float u = 1.0f + e;
    float l;
    asm("lg2.approx.ftz.f32 %0, %1;" : "=f"(l) : "f"(u));
    return fmaf(l, 0.6931471805599453f, m);
}

__device__ __forceinline__ uint32_t packh2(float lo, float hi) {
    __half2 h = __floats2half2_rn(lo, hi);
    return *(uint32_t*)&h;
}

__device__ __forceinline__ uint32_t smem_u32(const void* p) {
    uint32_t a;
    asm("{ .reg .u64 t; cvta.to.shared.u64 t, %1; cvt.u32.u64 %0, t; }" : "=r"(a) : "l"(p));
    return a;
}

__device__ __forceinline__ void mma_f16(float& d0, float& d1, float& d2, float& d3,
                                        uint32_t a0, uint32_t a1, uint32_t a2, uint32_t a3,
                                        uint32_t b0, uint32_t b1)
{
    asm volatile("mma.sync.aligned.m16n8k16.row.col.f32.f16.f16.f32 "
                 "{%0,%1,%2,%3}, {%4,%5,%6,%7}, {%8,%9}, {%0,%1,%2,%3};"
                 : "+f"(d0), "+f"(d1), "+f"(d2), "+f"(d3)
                 : "r"(a0), "r"(a1), "r"(a2), "r"(a3), "r"(b0), "r"(b1));
}

__device__ __forceinline__ void ldmatrix_x4(uint32_t& r0, uint32_t& r1,
                                            uint32_t& r2, uint32_t& r3, uint32_t addr)
{
    asm volatile("ldmatrix.sync.aligned.m8n8.x4.shared.b16 {%0,%1,%2,%3}, [%4];"
                 : "=r"(r0), "=r"(r1), "=r"(r2), "=r"(r3) : "r"(addr));
}

// pack W[k][n] (fp32 row-major) into fragment-ordered fp16 words in smem
// word(kp,n) = half2(W[2kp][n], W[2kp+1][n])
// dst word idx: ((ks*8 + j2)*32 + g*4 + tg)*4 + jlo*2 + bsel
__device__ __forceinline__ void stage_frag(const float* __restrict__ src,
                                           uint32_t* __restrict__ dst, int tid)
{
    #pragma unroll
    for (int i = 0; i < 8; i++) {
        int item = i * THREADS + tid;              // 2048 items
        int kp = item >> 5;
        int n4 = item & 31;
        float4 w0 = *(const float4*)(src + (size_t)(2 * kp)     * NH + 4 * n4);
        float4 w1 = *(const float4*)(src + (size_t)(2 * kp + 1) * NH + 4 * n4);
        int ks = kp >> 3, tg = kp & 3, bsel = (kp >> 2) & 1;
        float e0[4] = {w0.x, w0.y, w0.z, w0.w};
        float e1[4] = {w1.x, w1.y, w1.z, w1.w};
        #pragma unroll
        for (int e = 0; e < 4; e++) {
            int n = 4 * n4 + e;
            int g = n & 7, j2 = n >> 4, jlo = (n >> 3) & 1;
            dst[(((ks * 8 + j2) * 32 + g * 4 + tg) * 4) + jlo * 2 + bsel] =
                packh2(e0[e], e1[e]);
        }
    }
}

__global__ void __launch_bounds__(THREADS, 2)
pairmlp_diet_kernel(const float* __restrict__ x,
                    const float* __restrict__ W1,
                    const float* __restrict__ b1,
                    const float* __restrict__ Wh,
                    const float* __restrict__ bh,
                    const float* __restrict__ Wout,
                    const float* __restrict__ bout,
                    const int*   __restrict__ rel_idx,
                    const int*   __restrict__ i_idx,
                    const int*   __restrict__ j_idx,
                    float*       __restrict__ out,
                    int ntiles)
{
    extern __shared__ uint32_t smw[];
    float* smf = (float*)smw;
    const int tid  = threadIdx.x;
    const int lane = tid & 31;
    const int wid  = tid >> 5;       // 0..7
    const int g    = lane >> 2;
    const int tg   = lane & 3;
    const int mt   = wid >> 1;       // pair group: warps 2mt, 2mt+1
    const int nhf  = wid & 1;        // n half
    const int t64  = tid & 63;
    const int p    = blockIdx.x / CTAS_PER_PAIR;
    const int slot = blockIdx.x % CTAS_PER_PAIR;
    const uint32_t sbase = smem_u32(smw);

    // ---- one-time staging (CTA-wide) ----
    stage_frag(Wh + ((size_t)0 * NPAIR + p) * NH * NH, smw + OFF_BF0, tid);
    stage_frag(Wh + ((size_t)1 * NPAIR + p) * NH * NH, smw + OFF_BF1, tid);
    {   // W1 fragments: single K-step (K=16, rows 6..15 zero)
        int kp = tid >> 5;           // 0..7
        int n4 = tid & 31;
        const float* w1src = W1 + (size_t)p * DIN * NH;
        float4 z = make_float4(0.f, 0.f, 0.f, 0.f);
        float4 w0 = (2 * kp + 0 < DIN) ? *(const float4*)(w1src + (2 * kp) * NH + 4 * n4) : z;
        float4 w1v = (2 * kp + 1 < DIN) ? *(const float4*)(w1src + (2 * kp + 1) * NH + 4 * n4) : z;
        int tgs = kp & 3, bsel = (kp >> 2) & 1;
        float e0[4] = {w0.x, w0.y, w0.z, w0.w};
        float e1[4] = {w1v.x, w1v.y, w1v.z, w1v.w};
        #pragma unroll
        for (int e = 0; e < 4; e++) {
            int n = 4 * n4 + e;
            int gg = n & 7, j2 = n >> 4, jlo = (n >> 3) & 1;
            smw[OFF_W1F + ((j2 * 32 + gg * 4 + tgs) * 4) + jlo * 2 + bsel] =
                packh2(e0[e], e1[e]);
        }
    }
    if (tid < NH) {
        smf[OFF_B1  + tid] = b1[p * NH + tid];
        smf[OFF_BH0 + tid] = bh[((size_t)0 * NPAIR + p) * NH + tid];
        smf[OFF_BH1 + tid] = bh[((size_t)1 * NPAIR + p) * NH + tid];
        smf[OFF_WO  + tid] = Wout[p * NH + tid];
    }
    int rel[DIN];
    #pragma unroll
    for (int d = 0; d < DIN; d++) rel[d] = rel_idx[p * DIN + d];
    const float bo = bout[p];
    const int ii = i_idx[p];
    const int jp = j_idx[p];

    // ldmatrix addresses for the two 16-row A tiles (validated pattern)
    const int arow_base = mt * 32 + ((lane >> 3) & 1) * 8 + (lane & 7);
    const uint32_t a_addr_t0 = sbase + (OFF_H + arow_base * LDHW + (lane >> 4) * 4) * 4;
    const uint32_t a_addr_t1 = a_addr_t0 + 16 * LDHW * 4;

    const uint32_t* bf0p = smw + OFF_BF0 + ((nhf * 4) * 32 + lane) * 4;
    const uint32_t* bf1p = smw + OFF_BF1 + ((nhf * 4) * 32 + lane) * 4;
    const uint32_t* bW1p = smw + OFF_W1F + ((nhf * 4) * 32 + lane) * 4;

    // ---- x prefetch for first tile ----
    float4 xreg;
    int tile = slot;
    if (tile < ntiles)
        xreg = ((const float4*)(x + (size_t)tile * TILE_M * NDIM))[tid];

    __syncthreads();                           // staging visible (CTA-wide, once)

    for (; tile < ntiles; tile += CTAS_PER_PAIR) {
        const int b0 = tile * TILE_M;
        ((float4*)(smf + OFF_X))[tid] = xreg;  // pair-local rows
        PBAR(mt);                              // x visible within pair

        // ---- xg pack (pair-local): rows 32mt..32mt+31 ----
        {
            const int r = mt * 32 + (t64 >> 1);
            if ((t64 & 1) == 0) {
                float xv0 = smf[OFF_X + r * 8 + rel[0]];
                float xv1 = smf[OFF_X + r * 8 + rel[1]];
                float xv2 = smf[OFF_X + r * 8 + rel[2]];
                float xv3 = smf[OFF_X + r * 8 + rel[3]];
                float xv4 = smf[OFF_X + r * 8 + rel[4]];
                float xv5 = smf[OFF_X + r * 8 + rel[5]];
                uint4 w;
                w.x = packh2(xv0, xv1);
                w.y = packh2(xv2, xv3);
                w.z = packh2(xv4, xv5);
                w.w = 0u;
                *(uint4*)(smw + OFF_H + r * LDHW) = w;
            } else {
                *(uint4*)(smw + OFF_H + r * LDHW + 4) = make_uint4(0u, 0u, 0u, 0u);
            }
        }
        PBAR(mt);                              // xg ready

        float acc[2][8][4];

        // ---- mainloop 0 (W1F, single K-step); acc init = b1 ----
        #pragma unroll
        for (int ntl = 0; ntl < 8; ntl++) {
            float2 bb = *(const float2*)(smf + OFF_B1 + nhf * 64 + ntl * 8 + 2 * tg);
            acc[0][ntl][0] = bb.x; acc[0][ntl][1] = bb.y;
            acc[0][ntl][2] = bb.x; acc[0][ntl][3] = bb.y;
            acc[1][ntl][0] = bb.x; acc[1][ntl][1] = bb.y;
            acc[1][ntl][2] = bb.x; acc[1][ntl][3] = bb.y;
        }

        {
            uint32_t a00, a01, a02, a03, a10, a11, a12, a13;
            ldmatrix_x4(a00, a01, a02, a03, a_addr_t0);
            ldmatrix_x4(a10, a11, a12, a13, a_addr_t1);
            #pragma unroll
            for (int jl = 0; jl < 4; jl++) {
                uint4 bf = *(const uint4*)(bW1p + jl * 128);
                mma_f16(acc[0][2*jl][0],   acc[0][2*jl][1],   acc[0][2*jl][2],   acc[0][2*jl][3],
                        a00, a01, a02, a03, bf.x, bf.y);
                mma_f16(acc[0][2*jl+1][0], acc[0][2*jl+1][1], acc[0][2*jl+1][2], acc[0][2*jl+1][3],
                        a00, a01, a02, a03, bf.z, bf.w);
                mma_f16(acc[1][2*jl][0],   acc[1][2*jl][1],   acc[1][2*jl][2],   acc[1][2*jl][3],
                        a10, a11, a12, a13, bf.x, bf.y);
                mma_f16(acc[1][2*jl+1][0], acc[1][2*jl+1][1], acc[1][2*jl+1][2], acc[1][2*jl+1][3],
                        a10, a11, a12, a13, bf.z, bf.w);
            }
        }

        // prefetch next x under ML0
        {
            int nt = tile + CTAS_PER_PAIR;
            if (nt < ntiles)
                xreg = ((const float4*)(x + (size_t)nt * TILE_M * NDIM))[tid];
        }
        PBAR(mt);                              // ML0 A-reads done

        // ---- epilogue 0: h1 = packh2(softplus(acc)) ----
        #pragma unroll
        for (int t = 0; t < 2; t++) {
            const int rbase = mt * 32 + t * 16;
            #pragma unroll
            for (int ntl = 0; ntl < 8; ntl++) {
                int w = (nhf * 64 + ntl * 8 + 2 * tg) >> 1;
                smw[OFF_H + (rbase + g    ) * LDHW + w] =
                    packh2(softplus_f(acc[t][ntl][0]), softplus_f(acc[t][ntl][1]));
                smw[OFF_H + (rbase + g + 8) * LDHW + w] =
                    packh2(softplus_f(acc[t][ntl][2]), softplus_f(acc[t][ntl][3]));
            }
        }
        PBAR(mt);                              // h1 ready

        // ---- mainloop 1 (BF0); acc init = bh0 ----
        #pragma unroll
        for (int ntl = 0; ntl < 8; ntl++) {
            float2 bb = *(const float2*)(smf + OFF_BH0 + nhf * 64 + ntl * 8 + 2 * tg);
            acc[0][ntl][0] = bb.x; acc[0][ntl][1] = bb.y;
            acc[0][ntl][2] = bb.x; acc[0][ntl][3] = bb.y;
            acc[1][ntl][0] = bb.x; acc[1][ntl][1] = bb.y;
            acc[1][ntl][2] = bb.x; acc[1][ntl][3] = bb.y;
        }

        #pragma unroll
        for (int ks = 0; ks < 8; ks++) {
            uint32_t a00, a01, a02, a03, a10, a11, a12, a13;
            ldmatrix_x4(a00, a01, a02, a03, a_addr_t0 + ks * 32);
            ldmatrix_x4(a10, a11, a12, a13, a_addr_t1 + ks * 32);
            #pragma unroll
            for (int jl = 0; jl < 4; jl++) {
                uint4 bf = *(const uint4*)(bf0p + (ks * 8 + jl) * 128);
                mma_f16(acc[0][2*jl][0],   acc[0][2*jl][1],   acc[0][2*jl][2],   acc[0][2*jl][3],
                        a00, a01, a02, a03, bf.x, bf.y);
                mma_f16(acc[0][2*jl+1][0], acc[0][2*jl+1][1], acc[0][2*jl+1][2], acc[0][2*jl+1][3],
                        a00, a01, a02, a03, bf.z, bf.w);
                mma_f16(acc[1][2*jl][0],   acc[1][2*jl][1],   acc[1][2*jl][2],   acc[1][2*jl][3],
                        a10, a11, a12, a13, bf.x, bf.y);
                mma_f16(acc[1][2*jl+1][0], acc[1][2*jl+1][1], acc[1][2*jl+1][2], acc[1][2*jl+1][3],
                        a10, a11, a12, a13, bf.z, bf.w);
            }
        }
        PBAR(mt);                              // all h1 reads done

        // ---- epilogue 1: h2 = packh2(softplus(acc)) ----
        #pragma unroll
        for (int t = 0; t < 2; t++) {
            const int rbase = mt * 32 + t * 16;
            #pragma unroll
            for (int ntl = 0; ntl < 8; ntl++) {
                int w = (nhf * 64 + ntl * 8 + 2 * tg) >> 1;
                smw[OFF_H + (rbase + g    ) * LDHW + w] =
                    packh2(softplus_f(acc[t][ntl][0]), softplus_f(acc[t][ntl][1]));
                smw[OFF_H + (rbase + g + 8) * LDHW + w] =
                    packh2(softplus_f(acc[t][ntl][2]), softplus_f(acc[t][ntl][3]));
            }
        }
        PBAR(mt);                              // h2 ready

        // ---- mainloop 2 (BF1); acc init = bh1 ----
        #pragma unroll
        for (int ntl = 0; ntl < 8; ntl++) {
            float2 bb = *(const float2*)(smf + OFF_BH1 + nhf * 64 + ntl * 8 + 2 * tg);
            acc[0][ntl][0] = bb.x; acc[0][ntl][1] = bb.y;
            acc[0][ntl][2] = bb.x; acc[0][ntl][3] = bb.y;
            acc[1][ntl][0] = bb.x; acc[1][ntl][1] = bb.y;
            acc[1][ntl][2] = bb.x; acc[1][ntl][3] = bb.y;
        }

        #pragma unroll
        for (int ks = 0; ks < 8; ks++) {
            uint32_t a00, a01, a02, a03, a10, a11, a12, a13;
            ldmatrix_x4(a00, a01, a02, a03, a_addr_t0 + ks * 32);
            ldmatrix_x4(a10, a11, a12, a13, a_addr_t1 + ks * 32);
            #pragma unroll
            for (int jl = 0; jl < 4; jl++) {
                uint4 bf = *(const uint4*)(bf1p + (ks * 8 + jl) * 128);
                mma_f16(acc[0][2*jl][0],   acc[0][2*jl][1],   acc[0][2*jl][2],   acc[0][2*jl][3],
                        a00, a01, a02, a03, bf.x, bf.y);
                mma_f16(acc[0][2*jl+1][0], acc[0][2*jl+1][1], acc[0][2*jl+1][2], acc[0][2*jl+1][3],
                        a00, a01, a02, a03, bf.z, bf.w);
                mma_f16(acc[1][2*jl][0],   acc[1][2*jl][1],   acc[1][2*jl][2],   acc[1][2*jl][3],
                        a10, a11, a12, a13, bf.x, bf.y);
                mma_f16(acc[1][2*jl+1][0], acc[1][2*jl+1][1], acc[1][2*jl+1][2], acc[1][2*jl+1][3],
                        a10, a11, a12, a13, bf.z, bf.w);
            }
        }

        // ---- final epilogue: softplus + Wout dot, reduce, write J ----
        float sA[2], sB[2];
        #pragma unroll
        for (int t = 0; t < 2; t++) {
            float a = 0.0f, b = 0.0f;
            #pragma unroll
            for (int ntl = 0; ntl < 8; ntl++) {
                float2 ww = *(const float2*)(smf + OFF_WO + nhf * 64 + ntl * 8 + 2 * tg);
                a = fmaf(softplus_f(acc[t][ntl][0]), ww.x, a);
                a = fmaf(softplus_f(acc[t][ntl][1]), ww.y, a);
                b = fmaf(softplus_f(acc[t][ntl][2]), ww.x, b);
                b = fmaf(softplus_f(acc[t][ntl][3]), ww.y, b);
            }
            a += __shfl_xor_sync(0xffffffffu, a, 1);
            a += __shfl_xor_sync(0xffffffffu, a, 2);
            b += __shfl_xor_sync(0xffffffffu, b, 1);
            b += __shfl_xor_sync(0xffffffffu, b, 2);
            sA[t] = a; sB[t] = b;
        }

        if (nhf == 1 && tg == 0) {
            #pragma unroll
            for (int t = 0; t < 2; t++) {
                smf[OFF_PR + mt * 32 + t * 16 + g    ] = sA[t];
                smf[OFF_PR + mt * 32 + t * 16 + g + 8] = sB[t];
            }
        }
        PBAR(mt);                              // PR ready (pair-local)
        if (nhf == 0 && tg == 0) {
            #pragma unroll
            for (int t = 0; t < 2; t++) {
                int rA = mt * 32 + t * 16 + g;
                float vA = sA[t] + smf[OFF_PR + rA    ] + bo;
                float vB = sB[t] + smf[OFF_PR + rA + 8] + bo;
                size_t mA = (size_t)(b0 + rA) * (NDIM * NDIM);
                out[mA + ii * NDIM + jp] =  vA;
                out[mA + jp * NDIM + ii] = -vA;
                size_t mB = mA + (size_t)8 * (NDIM * NDIM);
                out[mB + ii * NDIM + jp] =  vB;
                out[mB + jp * NDIM + ii] = -vB;
            }
        }
    }
}

__global__ void zero_diag_kernel(float* __restrict__ out, int batch)
{
    int t = blockIdx.x * blockDim.x + threadIdx.x;
    if (t < batch * NDIM) {
        int b = t >> 3;
        int d = t & 7;
        out[(size_t)b * (NDIM * NDIM) + d * (NDIM + 1)] = 0.0f;
    }
}

extern "C" void kernel_launch(void* const* d_in, const int* in_sizes, int n_in,
                              void* d_out, int out_size)
{
    const float* x    = (const float*)d_in[0];
    const float* W1   = (const float*)d_in[1];
    const float* b1   = (const float*)d_in[2];
    const float* Wh   = (const float*)d_in[3];
    const float* bh   = (const float*)d_in[4];
    const float* Wout = (const float*)d_in[5];
    const float* bout = (const float*)d_in[6];
    const int*   rel  = (const int*)d_in[7];
    const int*   iidx = (const int*)d_in[8];
    const int*   jidx = (const int*)d_in[9];
    float* out = (float*)d_out;

    const int batch  = in_sizes[0] / NDIM;
    const int ntiles = batch / TILE_M;

    cudaFuncSetAttribute(pairmlp_diet_kernel,
                         cudaFuncAttributeMaxDynamicSharedMemorySize, SMEM_BYTES);

    zero_diag_kernel<<<(batch * NDIM + 255) / 256, 256>>>(out, batch);

    pairmlp_diet_kernel<<<NPAIR * CTAS_PER_PAIR, THREADS, SMEM_BYTES>>>(
        x, W1, b1, Wh, bh, Wout, bout, rel, iidx, jidx, out, ntiles);
}

// round 17
// speedup vs baseline: 1.3680x; 1.3680x over previous
#include <cuda_runtime.h>
#include <cuda_fp16.h>
#include <cstdint>

#define NDIM   8
#define NPAIR  28
#define NH     128
#define DIN    6
#define TILE_M 128
#define THREADS 256
#define CTAS_PER_PAIR 10
#define LDHW   68            // h row stride in 32-bit words, conflict-free

// ---- smem layout (32-bit word offsets) ----
#define OFF_BF0  0                       // 8192 words (128x128 fp16 fragments)
#define OFF_BF1  8192
#define OFF_H    16384                   // 128*68 = 8704 (words 0..7 double as xg)
#define OFF_X    25088                   // 128*8 fp32 = 1024
#define OFF_W1F  26112                   // 1024 words: W1 one-K-step fragments (K=16 padded)
#define OFF_B1   27136
#define OFF_BH0  27264
#define OFF_BH1  27392
#define OFF_WO   27520
#define OFF_PR   27648
#define SMEM_WORDS 27776
#define SMEM_BYTES (SMEM_WORDS * 4)      // 111104 -> 2 CTAs/SM

// pair-group barrier: 64 threads (warps 2*mt, 2*mt+1), ids 1..4
#define PBAR(id) asm volatile("bar.sync %0, 64;" :: "r"((id) + 1) : "memory")

// softplus = max(v,0) + ln2*lg2(1 + 2^(-|v|*log2e)) : 6 instrs, 2 MUFU
__device__ __forceinline__ float softplus_f(float v) {
    float m = fmaxf(v, 0.0f);
    float y = -fabsf(v) * 1.4426950408889634f;     // folds into one FMUL
    float e;
    asm("ex2.approx.ftz.f32 %0, %1;" : "=f"(e) : "f"(y));
    float u = 1.0f + e;
    float l;
    asm("lg2.approx.ftz.f32 %0, %1;" : "=f"(l) : "f"(u));
    return fmaf(l, 0.6931471805599453f, m);
}

__device__ __forceinline__ uint32_t packh2(float lo, float hi) {
    __half2 h = __floats2half2_rn(lo, hi);
    return *(uint32_t*)&h;
}

__device__ __forceinline__ uint32_t smem_u32(const void* p) {
    uint32_t a;
    asm("{ .reg .u64 t; cvta.to.shared.u64 t, %1; cvt.u32.u64 %0, t; }" : "=r"(a) : "l"(p));
    return a;
}

__device__ __forceinline__ void mma_f16(float& d0, float& d1, float& d2, float& d3,
                                        uint32_t a0, uint32_t a1, uint32_t a2, uint32_t a3,
                                        uint32_t b0, uint32_t b1)
{
    asm volatile("mma.sync.aligned.m16n8k16.row.col.f32.f16.f16.f32 "
                 "{%0,%1,%2,%3}, {%4,%5,%6,%7}, {%8,%9}, {%0,%1,%2,%3};"
                 : "+f"(d0), "+f"(d1), "+f"(d2), "+f"(d3)
                 : "r"(a0), "r"(a1), "r"(a2), "r"(a3), "r"(b0), "r"(b1));
}

__device__ __forceinline__ void ldmatrix_x4(uint32_t& r0, uint32_t& r1,
                                            uint32_t& r2, uint32_t& r3, uint32_t addr)
{
    asm volatile("ldmatrix.sync.aligned.m8n8.x4.shared.b16 {%0,%1,%2,%3}, [%4];"
                 : "=r"(r0), "=r"(r1), "=r"(r2), "=r"(r3) : "r"(addr));
}

// pack W[k][n] (fp32 row-major) into fragment-ordered fp16 words in smem
// word(kp,n) = half2(W[2kp][n], W[2kp+1][n])
// dst word idx: ((ks*8 + j2)*32 + g*4 + tg)*4 + jlo*2 + bsel
__device__ __forceinline__ void stage_frag(const float* __restrict__ src,
                                           uint32_t* __restrict__ dst, int tid)
{
    #pragma unroll
    for (int i = 0; i < 8; i++) {
        int item = i * THREADS + tid;              // 2048 items
        int kp = item >> 5;
        int n4 = item & 31;
        float4 w0 = *(const float4*)(src + (size_t)(2 * kp)     * NH + 4 * n4);
        float4 w1 = *(const float4*)(src + (size_t)(2 * kp + 1) * NH + 4 * n4);
        int ks = kp >> 3, tg = kp & 3, bsel = (kp >> 2) & 1;
        float e0[4] = {w0.x, w0.y, w0.z, w0.w};
        float e1[4] = {w1.x, w1.y, w1.z, w1.w};
        #pragma unroll
        for (int e = 0; e < 4; e++) {
            int n = 4 * n4 + e;
            int g = n & 7, j2 = n >> 4, jlo = (n >> 3) & 1;
            dst[(((ks * 8 + j2) * 32 + g * 4 + tg) * 4) + jlo * 2 + bsel] =
                packh2(e0[e], e1[e]);
        }
    }
}

__global__ void __launch_bounds__(THREADS, 2)
pairmlp_sp6_kernel(const float* __restrict__ x,
                   const float* __restrict__ W1,
                   const float* __restrict__ b1,
                   const float* __restrict__ Wh,
                   const float* __restrict__ bh,
                   const float* __restrict__ Wout,
                   const float* __restrict__ bout,
                   const int*   __restrict__ rel_idx,
                   const int*   __restrict__ i_idx,
                   const int*   __restrict__ j_idx,
                   float*       __restrict__ out,
                   int ntiles)
{
    extern __shared__ uint32_t smw[];
    float* smf = (float*)smw;
    const int tid  = threadIdx.x;
    const int lane = tid & 31;
    const int wid  = tid >> 5;       // 0..7
    const int g    = lane >> 2;
    const int tg   = lane & 3;
    const int mt   = wid >> 1;       // pair group: warps 2mt, 2mt+1
    const int nhf  = wid & 1;        // n half
    const int t64  = tid & 63;
    const int p    = blockIdx.x / CTAS_PER_PAIR;
    const int slot = blockIdx.x % CTAS_PER_PAIR;
    const uint32_t sbase = smem_u32(smw);

    // ---- one-time staging (CTA-wide) ----
    stage_frag(Wh + ((size_t)0 * NPAIR + p) * NH * NH, smw + OFF_BF0, tid);
    stage_frag(Wh + ((size_t)1 * NPAIR + p) * NH * NH, smw + OFF_BF1, tid);
    {   // W1 fragments: single K-step (K=16, rows 6..15 zero)
        int kp = tid >> 5;           // 0..7
        int n4 = tid & 31;
        const float* w1src = W1 + (size_t)p * DIN * NH;
        float4 z = make_float4(0.f, 0.f, 0.f, 0.f);
        float4 w0 = (2 * kp + 0 < DIN) ? *(const float4*)(w1src + (2 * kp) * NH + 4 * n4) : z;
        float4 w1v = (2 * kp + 1 < DIN) ? *(const float4*)(w1src + (2 * kp + 1) * NH + 4 * n4) : z;
        int tgs = kp & 3, bsel = (kp >> 2) & 1;
        float e0[4] = {w0.x, w0.y, w0.z, w0.w};
        float e1[4] = {w1v.x, w1v.y, w1v.z, w1v.w};
        #pragma unroll
        for (int e = 0; e < 4; e++) {
            int n = 4 * n4 + e;
            int gg = n & 7, j2 = n >> 4, jlo = (n >> 3) & 1;
            smw[OFF_W1F + ((j2 * 32 + gg * 4 + tgs) * 4) + jlo * 2 + bsel] =
                packh2(e0[e], e1[e]);
        }
    }
    if (tid < NH) {
        smf[OFF_B1  + tid] = b1[p * NH + tid];
        smf[OFF_BH0 + tid] = bh[((size_t)0 * NPAIR + p) * NH + tid];
        smf[OFF_BH1 + tid] = bh[((size_t)1 * NPAIR + p) * NH + tid];
        smf[OFF_WO  + tid] = Wout[p * NH + tid];
    }
    int rel[DIN];
    #pragma unroll
    for (int d = 0; d < DIN; d++) rel[d] = rel_idx[p * DIN + d];
    const float bo = bout[p];
    const int ii = i_idx[p];
    const int jp = j_idx[p];

    // ldmatrix addresses for the two 16-row A tiles (validated pattern)
    const int arow_base = mt * 32 + ((lane >> 3) & 1) * 8 + (lane & 7);
    const uint32_t a_addr_t0 = sbase + (OFF_H + arow_base * LDHW + (lane >> 4) * 4) * 4;
    const uint32_t a_addr_t1 = a_addr_t0 + 16 * LDHW * 4;

    const uint32_t* bf0p = smw + OFF_BF0 + ((nhf * 4) * 32 + lane) * 4;
    const uint32_t* bf1p = smw + OFF_BF1 + ((nhf * 4) * 32 + lane) * 4;
    const uint32_t* bW1p = smw + OFF_W1F + ((nhf * 4) * 32 + lane) * 4;

    // ---- x prefetch for first tile ----
    float4 xreg;
    int tile = slot;
    if (tile < ntiles)
        xreg = ((const float4*)(x + (size_t)tile * TILE_M * NDIM))[tid];

    __syncthreads();                           // staging visible (CTA-wide, once)

    for (; tile < ntiles; tile += CTAS_PER_PAIR) {
        const int b0 = tile * TILE_M;
        ((float4*)(smf + OFF_X))[tid] = xreg;  // pair-local rows
        PBAR(mt);                              // x visible within pair

        // ---- xg pack (pair-local): rows 32mt..32mt+31 ----
        {
            const int r = mt * 32 + (t64 >> 1);
            if ((t64 & 1) == 0) {
                float xv0 = smf[OFF_X + r * 8 + rel[0]];
                float xv1 = smf[OFF_X + r * 8 + rel[1]];
                float xv2 = smf[OFF_X + r * 8 + rel[2]];
                float xv3 = smf[OFF_X + r * 8 + rel[3]];
                float xv4 = smf[OFF_X + r * 8 + rel[4]];
                float xv5 = smf[OFF_X + r * 8 + rel[5]];
                uint4 w;
                w.x = packh2(xv0, xv1);
                w.y = packh2(xv2, xv3);
                w.z = packh2(xv4, xv5);
                w.w = 0u;
                *(uint4*)(smw + OFF_H + r * LDHW) = w;
            } else {
                *(uint4*)(smw + OFF_H + r * LDHW + 4) = make_uint4(0u, 0u, 0u, 0u);
            }
        }
        PBAR(mt);                              // xg ready

        float acc[2][8][4];

        // ---- mainloop 0 (W1F, single K-step) ----
        #pragma unroll
        for (int t = 0; t < 2; t++)
            #pragma unroll
            for (int n = 0; n < 8; n++)
                #pragma unroll
                for (int q = 0; q < 4; q++) acc[t][n][q] = 0.0f;

        {
            uint32_t a00, a01, a02, a03, a10, a11, a12, a13;
            ldmatrix_x4(a00, a01, a02, a03, a_addr_t0);
            ldmatrix_x4(a10, a11, a12, a13, a_addr_t1);
            #pragma unroll
            for (int jl = 0; jl < 4; jl++) {
                uint4 bf = *(const uint4*)(bW1p + jl * 128);
                mma_f16(acc[0][2*jl][0],   acc[0][2*jl][1],   acc[0][2*jl][2],   acc[0][2*jl][3],
                        a00, a01, a02, a03, bf.x, bf.y);
                mma_f16(acc[0][2*jl+1][0], acc[0][2*jl+1][1], acc[0][2*jl+1][2], acc[0][2*jl+1][3],
                        a00, a01, a02, a03, bf.z, bf.w);
                mma_f16(acc[1][2*jl][0],   acc[1][2*jl][1],   acc[1][2*jl][2],   acc[1][2*jl][3],
                        a10, a11, a12, a13, bf.x, bf.y);
                mma_f16(acc[1][2*jl+1][0], acc[1][2*jl+1][1], acc[1][2*jl+1][2], acc[1][2*jl+1][3],
                        a10, a11, a12, a13, bf.z, bf.w);
            }
        }

        // prefetch next x under ML0
        {
            int nt = tile + CTAS_PER_PAIR;
            if (nt < ntiles)
                xreg = ((const float4*)(x + (size_t)nt * TILE_M * NDIM))[tid];
        }
        PBAR(mt);                              // ML0 A-reads done

        // ---- epilogue 0: h1 = packh2(softplus(acc + b1)) ----
        #pragma unroll
        for (int t = 0; t < 2; t++) {
            const int rbase = mt * 32 + t * 16;
            #pragma unroll
            for (int ntl = 0; ntl < 8; ntl++) {
                int n0 = nhf * 64 + ntl * 8 + 2 * tg;
                float2 bb = *(const float2*)(smf + OFF_B1 + n0);
                int w = n0 >> 1;
                smw[OFF_H + (rbase + g    ) * LDHW + w] =
                    packh2(softplus_f(acc[t][ntl][0] + bb.x), softplus_f(acc[t][ntl][1] + bb.y));
                smw[OFF_H + (rbase + g + 8) * LDHW + w] =
                    packh2(softplus_f(acc[t][ntl][2] + bb.x), softplus_f(acc[t][ntl][3] + bb.y));
            }
        }
        PBAR(mt);                              // h1 ready

        // ---- mainloop 1 (BF0): one B load serves 2 m-tiles ----
        #pragma unroll
        for (int t = 0; t < 2; t++)
            #pragma unroll
            for (int n = 0; n < 8; n++)
                #pragma unroll
                for (int q = 0; q < 4; q++) acc[t][n][q] = 0.0f;

        #pragma unroll
        for (int ks = 0; ks < 8; ks++) {
            uint32_t a00, a01, a02, a03, a10, a11, a12, a13;
            ldmatrix_x4(a00, a01, a02, a03, a_addr_t0 + ks * 32);
            ldmatrix_x4(a10, a11, a12, a13, a_addr_t1 + ks * 32);
            #pragma unroll
            for (int jl = 0; jl < 4; jl++) {
                uint4 bf = *(const uint4*)(bf0p + (ks * 8 + jl) * 128);
                mma_f16(acc[0][2*jl][0],   acc[0][2*jl][1],   acc[0][2*jl][2],   acc[0][2*jl][3],
                        a00, a01, a02, a03, bf.x, bf.y);
                mma_f16(acc[0][2*jl+1][0], acc[0][2*jl+1][1], acc[0][2*jl+1][2], acc[0][2*jl+1][3],
                        a00, a01, a02, a03, bf.z, bf.w);
                mma_f16(acc[1][2*jl][0],   acc[1][2*jl][1],   acc[1][2*jl][2],   acc[1][2*jl][3],
                        a10, a11, a12, a13, bf.x, bf.y);
                mma_f16(acc[1][2*jl+1][0], acc[1][2*jl+1][1], acc[1][2*jl+1][2], acc[1][2*jl+1][3],
                        a10, a11, a12, a13, bf.z, bf.w);
            }
        }
        PBAR(mt);                              // all h1 reads done

        // ---- epilogue 1: h2 = packh2(softplus(acc + bh0)) ----
        #pragma unroll
        for (int t = 0; t < 2; t++) {
            const int rbase = mt * 32 + t * 16;
            #pragma unroll
            for (int ntl = 0; ntl < 8; ntl++) {
                int n0 = nhf * 64 + ntl * 8 + 2 * tg;
                float2 bb = *(const float2*)(smf + OFF_BH0 + n0);
                int w = n0 >> 1;
                smw[OFF_H + (rbase + g    ) * LDHW + w] =
                    packh2(softplus_f(acc[t][ntl][0] + bb.x), softplus_f(acc[t][ntl][1] + bb.y));
                smw[OFF_H + (rbase + g + 8) * LDHW + w] =
                    packh2(softplus_f(acc[t][ntl][2] + bb.x), softplus_f(acc[t][ntl][3] + bb.y));
            }
        }
        PBAR(mt);                              // h2 ready

        // ---- mainloop 2 (BF1) ----
        #pragma unroll
        for (int t = 0; t < 2; t++)
            #pragma unroll
            for (int n = 0; n < 8; n++)
                #pragma unroll
                for (int q = 0; q < 4; q++) acc[t][n][q] = 0.0f;

        #pragma unroll
        for (int ks = 0; ks < 8; ks++) {
            uint32_t a00, a01, a02, a03, a10, a11, a12, a13;
            ldmatrix_x4(a00, a01, a02, a03, a_addr_t0 + ks * 32);
            ldmatrix_x4(a10, a11, a12, a13, a_addr_t1 + ks * 32);
            #pragma unroll
            for (int jl = 0; jl < 4; jl++) {
                uint4 bf = *(const uint4*)(bf1p + (ks * 8 + jl) * 128);
                mma_f16(acc[0][2*jl][0],   acc[0][2*jl][1],   acc[0][2*jl][2],   acc[0][2*jl][3],
                        a00, a01, a02, a03, bf.x, bf.y);
                mma_f16(acc[0][2*jl+1][0], acc[0][2*jl+1][1], acc[0][2*jl+1][2], acc[0][2*jl+1][3],
                        a00, a01, a02, a03, bf.z, bf.w);
                mma_f16(acc[1][2*jl][0],   acc[1][2*jl][1],   acc[1][2*jl][2],   acc[1][2*jl][3],
                        a10, a11, a12, a13, bf.x, bf.y);
                mma_f16(acc[1][2*jl+1][0], acc[1][2*jl+1][1], acc[1][2*jl+1][2], acc[1][2*jl+1][3],
                        a10, a11, a12, a13, bf.z, bf.w);
            }
        }

        // ---- final epilogue: softplus + Wout dot, reduce, write J ----
        float sA[2], sB[2];
        #pragma unroll
        for (int t = 0; t < 2; t++) {
            float a = 0.0f, b = 0.0f;
            #pragma unroll
            for (int ntl = 0; ntl < 8; ntl++) {
                int n0 = nhf * 64 + ntl * 8 + 2 * tg;
                float2 bb = *(const float2*)(smf + OFF_BH1 + n0);
                float2 ww = *(const float2*)(smf + OFF_WO  + n0);
                a = fmaf(softplus_f(acc[t][ntl][0] + bb.x), ww.x, a);
                a = fmaf(softplus_f(acc[t][ntl][1] + bb.y), ww.y, a);
                b = fmaf(softplus_f(acc[t][ntl][2] + bb.x), ww.x, b);
                b = fmaf(softplus_f(acc[t][ntl][3] + bb.y), ww.y, b);
            }
            a += __shfl_xor_sync(0xffffffffu, a, 1);
            a += __shfl_xor_sync(0xffffffffu, a, 2);
            b += __shfl_xor_sync(0xffffffffu, b, 1);
            b += __shfl_xor_sync(0xffffffffu, b, 2);
            sA[t] = a; sB[t] = b;
        }

        if (nhf == 1 && tg == 0) {
            #pragma unroll
            for (int t = 0; t < 2; t++) {
                smf[OFF_PR + mt * 32 + t * 16 + g    ] = sA[t];
                smf[OFF_PR + mt * 32 + t * 16 + g + 8] = sB[t];
            }
        }
        PBAR(mt);                              // PR ready (pair-local)
        if (nhf == 0 && tg == 0) {
            #pragma unroll
            for (int t = 0; t < 2; t++) {
                int rA = mt * 32 + t * 16 + g;
                float vA = sA[t] + smf[OFF_PR + rA    ] + bo;
                float vB = sB[t] + smf[OFF_PR + rA + 8] + bo;
                size_t mA = (size_t)(b0 + rA) * (NDIM * NDIM);
                out[mA + ii * NDIM + jp] =  vA;
                out[mA + jp * NDIM + ii] = -vA;
                size_t mB = mA + (size_t)8 * (NDIM * NDIM);
                out[mB + ii * NDIM + jp] =  vB;
                out[mB + jp * NDIM + ii] = -vB;
            }
        }
    }
}

__global__ void zero_diag_kernel(float* __restrict__ out, int batch)
{
    int t = blockIdx.x * blockDim.x + threadIdx.x;
    if (t < batch * NDIM) {
        int b = t >> 3;
        int d = t & 7;
        out[(size_t)b * (NDIM * NDIM) + d * (NDIM + 1)] = 0.0f;
    }
}

extern "C" void kernel_launch(void* const* d_in, const int* in_sizes, int n_in,
                              void* d_out, int out_size)
{
    const float* x    = (const float*)d_in[0];
    const float* W1   = (const float*)d_in[1];
    const float* b1   = (const float*)d_in[2];
    const float* Wh   = (const float*)d_in[3];
    const float* bh   = (const float*)d_in[4];
    const float* Wout = (const float*)d_in[5];
    const float* bout = (const float*)d_in[6];
    const int*   rel  = (const int*)d_in[7];
    const int*   iidx = (const int*)d_in[8];
    const int*   jidx = (const int*)d_in[9];
    float* out = (float*)d_out;

    const int batch  = in_sizes[0] / NDIM;
    const int ntiles = batch / TILE_M;

    cudaFuncSetAttribute(pairmlp_sp6_kernel,
                         cudaFuncAttributeMaxDynamicSharedMemorySize, SMEM_BYTES);

    zero_diag_kernel<<<(batch * NDIM + 255) / 256, 256>>>(out, batch);

    pairmlp_sp6_kernel<<<NPAIR * CTAS_PER_PAIR, THREADS, SMEM_BYTES>>>(
        x, W1, b1, Wh, bh, Wout, bout, rel, iidx, jidx, out, ntiles);
}